// round 1
// baseline (speedup 1.0000x reference)
#include <cuda_runtime.h>

// ---------------------------------------------------------------------------
// CrossViewSwapAttention — fp32, f32x2-packed attention mainloop.
// Shapes (fixed by the problem):
//   q: (1,6,8,8,8,8,128)   -> qf  (L=64, Nq=384, d=128)
//   k,v: (1,6,8,8,8,10,128)-> kf  (L=64, Nk=480, d=128)
//   heads m=4, dh=32, inner=128
//   out: (1,8,8,8,8,128) = 524288 floats
// ---------------------------------------------------------------------------

#define NQ_ROWS  24576   // 64*384
#define NK_ROWS  30720   // 64*480
#define D        128

__device__ float g_qp [NQ_ROWS * D];
__device__ float g_kp [NK_ROWS * D];
__device__ float g_vp [NK_ROWS * D];
__device__ float g_att[NQ_ROWS * D];

typedef unsigned long long u64;

__device__ __forceinline__ u64 fma2(u64 a, u64 b, u64 c) {
    u64 d;
    asm("fma.rn.f32x2 %0, %1, %2, %3;" : "=l"(d) : "l"(a), "l"(b), "l"(c));
    return d;
}
__device__ __forceinline__ u64 mul2(u64 a, u64 b) {
    u64 d;
    asm("mul.rn.f32x2 %0, %1, %2;" : "=l"(d) : "l"(a), "l"(b));
    return d;
}
__device__ __forceinline__ u64 pack2(float x, float y) {
    u64 d;
    asm("mov.b64 %0, {%1, %2};" : "=l"(d) : "f"(x), "f"(y));
    return d;
}
__device__ __forceinline__ float2 unpack2(u64 v) {
    float2 r;
    asm("mov.b64 {%0, %1}, %2;" : "=f"(r.x), "=f"(r.y) : "l"(v));
    return r;
}

// ---------------------------------------------------------------------------
// Kernel A: fused LayerNorm + Linear (d=128 -> inner=128), 16 rows per block.
// Row r of the flattened [L*N, 128] matrix maps back into the input tensor:
//   L = r / rowsPerL ; N = r % rowsPerL ; n = N / perN ; wi = N % perN
//   input row = n*64*perN + L*perN + wi      (derived from the einops reshape)
// dst_sel: 0 -> g_qp, 1 -> g_kp, 2 -> g_vp
// ---------------------------------------------------------------------------
__global__ __launch_bounds__(128)
void ln_linear_kernel(const float* __restrict__ x,
                      const float* __restrict__ gamma,
                      const float* __restrict__ beta,
                      const float* __restrict__ W,    // [128 in][128 out]
                      const float* __restrict__ blin, // [128]
                      int dst_sel, int rowsPerL, int perN)
{
    __shared__ float xn_s[16][128];
    const int tid  = threadIdx.x;
    const int warp = tid >> 5;
    const int lane = tid & 31;
    const int rbase = blockIdx.x * 16;

    float* __restrict__ out = (dst_sel == 0) ? g_qp : (dst_sel == 1) ? g_kp : g_vp;

    const float g0 = gamma[lane],     g1 = gamma[lane + 32],
                g2 = gamma[lane + 64], g3 = gamma[lane + 96];
    const float b0 = beta[lane],      b1 = beta[lane + 32],
                b2 = beta[lane + 64], b3 = beta[lane + 96];

    // Phase 1: each warp normalizes 4 rows (warp-shuffle reductions).
    #pragma unroll
    for (int rr = 0; rr < 4; rr++) {
        const int r   = warp * 4 + rr;
        const int row = rbase + r;
        const int L   = row / rowsPerL;
        const int N   = row - L * rowsPerL;
        const int nn  = N / perN;
        const int wi  = N - nn * perN;
        const float* xr = x + ((nn * 64 + L) * perN + wi) * D;

        const float v0 = xr[lane], v1 = xr[lane + 32],
                    v2 = xr[lane + 64], v3 = xr[lane + 96];
        float s = v0 + v1 + v2 + v3;
        #pragma unroll
        for (int o = 16; o; o >>= 1) s += __shfl_xor_sync(0xffffffffu, s, o);
        const float mu = s * (1.0f / 128.0f);
        const float d0 = v0 - mu, d1 = v1 - mu, d2 = v2 - mu, d3 = v3 - mu;
        float sq = d0 * d0 + d1 * d1 + d2 * d2 + d3 * d3;
        #pragma unroll
        for (int o = 16; o; o >>= 1) sq += __shfl_xor_sync(0xffffffffu, sq, o);
        const float rstd = rsqrtf(sq * (1.0f / 128.0f) + 1e-5f);

        xn_s[r][lane]      = d0 * rstd * g0 + b0;
        xn_s[r][lane + 32] = d1 * rstd * g1 + b1;
        xn_s[r][lane + 64] = d2 * rstd * g2 + b2;
        xn_s[r][lane + 96] = d3 * rstd * g3 + b3;
    }
    __syncthreads();

    // Phase 2: each thread owns output column c, 16-row register tile.
    const int c = tid;
    float acc[16];
    const float bb = blin[c];
    #pragma unroll
    for (int r = 0; r < 16; r++) acc[r] = bb;

    #pragma unroll 4
    for (int j = 0; j < 128; j++) {
        const float w = W[j * 128 + c];
        #pragma unroll
        for (int r = 0; r < 16; r++) acc[r] = fmaf(xn_s[r][j], w, acc[r]);
    }
    #pragma unroll
    for (int r = 0; r < 16; r++) out[(rbase + r) * D + c] = acc[r];
}

// ---------------------------------------------------------------------------
// Kernel B: attention. Grid 768 = 4 heads * 64 L * 3 q-tiles, 128 thr/block.
// Each thread owns one q row (dh=32 in f32x2 regs), streams K/V through SMEM
// in 96-key chunks, softmax without max-subtraction (|s| <~ 8, exp safe).
// ---------------------------------------------------------------------------
#define KCHUNK 96

__global__ __launch_bounds__(128)
void attn_kernel(const float* __restrict__ scale_ptr)
{
    __shared__ float4 ks4[KCHUNK * 8];
    __shared__ float4 vs4[KCHUNK * 8];

    const int bx  = blockIdx.x;
    const int h   = bx & 3;
    const int l   = (bx >> 2) & 63;
    const int qt  = bx >> 8;
    const int tid = threadIdx.x;
    const int qi  = qt * 128 + tid;

    const float coef = scale_ptr[0] * 0.17677669529663687f; // attn_scale * dh^-0.5

    const u64* qrp = (const u64*)(g_qp + (l * 384 + qi) * D + h * 32);
    u64 qr[16];
    #pragma unroll
    for (int i = 0; i < 16; i++) qr[i] = qrp[i];

    u64 acc[16];
    #pragma unroll
    for (int i = 0; i < 16; i++) acc[i] = 0ULL;
    float lsum = 0.0f;

    const float* kbase = g_kp + l * 480 * D + h * 32;
    const float* vbase = g_vp + l * 480 * D + h * 32;

    for (int c0 = 0; c0 < 480; c0 += KCHUNK) {
        __syncthreads();
        #pragma unroll
        for (int i = 0; i < (KCHUNK * 8) / 128; i++) {       // 6 iters
            const int idx = tid + i * 128;
            const int row = idx >> 3;
            const int c4  = idx & 7;
            ks4[idx] = *(const float4*)(kbase + (c0 + row) * D + c4 * 4);
            vs4[idx] = *(const float4*)(vbase + (c0 + row) * D + c4 * 4);
        }
        __syncthreads();

        #pragma unroll 2
        for (int kk = 0; kk < KCHUNK; kk++) {
            const u64* kr = (const u64*)(ks4 + kk * 8);
            u64 s2 = 0ULL;
            #pragma unroll
            for (int i = 0; i < 16; i++) s2 = fma2(qr[i], kr[i], s2);
            const float2 sp = unpack2(s2);
            const float p = __expf((sp.x + sp.y) * coef);
            lsum += p;
            const u64 p2 = pack2(p, p);
            const u64* vr = (const u64*)(vs4 + kk * 8);
            #pragma unroll
            for (int i = 0; i < 16; i++) acc[i] = fma2(p2, vr[i], acc[i]);
        }
    }

    const float inv = 1.0f / lsum;
    const u64 inv2 = pack2(inv, inv);
    u64* op = (u64*)(g_att + (l * 384 + qi) * D + h * 32);
    #pragma unroll
    for (int i = 0; i < 16; i++) op[i] = mul2(acc[i], inv2);
}

// ---------------------------------------------------------------------------
// Kernel C: mean over n (commutes with the affine proj) + Wp + bp + skip.
// 4096 output rows, 16 per block. Output row o = L*64 + (W1*8+W2).
// ---------------------------------------------------------------------------
__global__ __launch_bounds__(128)
void proj_kernel(const float* __restrict__ Wp,
                 const float* __restrict__ bp,
                 const float* __restrict__ skip,
                 float* __restrict__ out)
{
    __shared__ float ab[16][128];
    const int tid   = threadIdx.x;
    const int obase = blockIdx.x * 16;

    #pragma unroll
    for (int r = 0; r < 16; r++) {
        const int o  = obase + r;
        const int L  = o >> 6;
        const int wi = o & 63;
        float s = 0.0f;
        #pragma unroll
        for (int n = 0; n < 6; n++)
            s += g_att[(L * 384 + n * 64 + wi) * D + tid];
        ab[r][tid] = s * (1.0f / 6.0f);
    }
    __syncthreads();

    const int c = tid;
    float acc[16];
    const float bb = bp[c];
    #pragma unroll
    for (int r = 0; r < 16; r++) acc[r] = bb;

    #pragma unroll 4
    for (int j = 0; j < 128; j++) {
        const float w = Wp[j * 128 + c];
        #pragma unroll
        for (int r = 0; r < 16; r++) acc[r] = fmaf(ab[r][j], w, acc[r]);
    }
    #pragma unroll
    for (int r = 0; r < 16; r++) {
        const int o = obase + r;
        out[o * D + c] = acc[r] + skip[o * D + c];
    }
}

// ---------------------------------------------------------------------------
extern "C" void kernel_launch(void* const* d_in, const int* in_sizes, int n_in,
                              void* d_out, int out_size)
{
    const float* q          = (const float*)d_in[0];
    const float* k          = (const float*)d_in[1];
    const float* v          = (const float*)d_in[2];
    const float* skip       = (const float*)d_in[3];
    const float* attn_scale = (const float*)d_in[4];
    const float* lnq_g = (const float*)d_in[5];
    const float* lnq_b = (const float*)d_in[6];
    const float* Wq    = (const float*)d_in[7];
    const float* bq    = (const float*)d_in[8];
    const float* lnk_g = (const float*)d_in[9];
    const float* lnk_b = (const float*)d_in[10];
    const float* Wk    = (const float*)d_in[11];
    const float* bk    = (const float*)d_in[12];
    const float* lnv_g = (const float*)d_in[13];
    const float* lnv_b = (const float*)d_in[14];
    const float* Wv    = (const float*)d_in[15];
    const float* bv    = (const float*)d_in[16];
    const float* Wp    = (const float*)d_in[17];
    const float* bp    = (const float*)d_in[18];
    float* out = (float*)d_out;

    // LN + Linear projections: q (384 rows/L, 64 per n), k/v (480 rows/L, 80 per n)
    ln_linear_kernel<<<NQ_ROWS / 16, 128>>>(q, lnq_g, lnq_b, Wq, bq, 0, 384, 64);
    ln_linear_kernel<<<NK_ROWS / 16, 128>>>(k, lnk_g, lnk_b, Wk, bk, 1, 480, 80);
    ln_linear_kernel<<<NK_ROWS / 16, 128>>>(v, lnv_g, lnv_b, Wv, bv, 2, 480, 80);

    // Attention: 4 heads * 64 L * 3 q-tiles
    attn_kernel<<<768, 128>>>(attn_scale);

    // Mean over views + output projection + skip
    proj_kernel<<<4096 / 16, 128>>>(Wp, bp, skip, out);
}

// round 3
// speedup vs baseline: 1.0047x; 1.0047x over previous
#include <cuda_runtime.h>

// ---------------------------------------------------------------------------
// CrossViewSwapAttention — fp32, f32x2 FMA-bound design.
//   q: (1,6,8,8,8,8,128)   -> qf  (L=64, Nq=384, d=128)
//   k,v: (1,6,8,8,8,10,128)-> kf  (L=64, Nk=480, d=128)
//   heads m=4, dh=32, inner=128; out: (1,8,8,8,8,128)
// ---------------------------------------------------------------------------

#define NQ_ROWS  24576   // 64*384
#define NK_ROWS  30720   // 64*480
#define D        128

__device__ float g_qp [NQ_ROWS * D];
__device__ float g_kp [NK_ROWS * D];
__device__ float g_vp [NK_ROWS * D];
__device__ float g_att[NQ_ROWS * D];

typedef unsigned long long u64;

__device__ __forceinline__ u64 fma2(u64 a, u64 b, u64 c) {
    u64 d;
    asm("fma.rn.f32x2 %0, %1, %2, %3;" : "=l"(d) : "l"(a), "l"(b), "l"(c));
    return d;
}
__device__ __forceinline__ u64 mul2(u64 a, u64 b) {
    u64 d;
    asm("mul.rn.f32x2 %0, %1, %2;" : "=l"(d) : "l"(a), "l"(b));
    return d;
}
__device__ __forceinline__ u64 pack2(float x, float y) {
    u64 d;
    asm("mov.b64 %0, {%1, %2};" : "=l"(d) : "f"(x), "f"(y));
    return d;
}
__device__ __forceinline__ float2 unpack2(u64 v) {
    float2 r;
    asm("mov.b64 {%0, %1}, %2;" : "=f"(r.x), "=f"(r.y) : "l"(v));
    return r;
}

// ---------------------------------------------------------------------------
// Kernel A: fused LayerNorm + Linear (128 -> 128), 32 rows per block.
// Phase 2 is a register-tiled GEMM: 8 row-groups x 16 col-groups of threads,
// each thread computes a 4-row x 8-col tile with f32x2 FMAs.
// Input row mapping (from einops reshape):
//   L = r / rowsPerL ; N = r % rowsPerL ; n = N / perN ; wi = N % perN
//   input row = n*64*perN + L*perN + wi
// ---------------------------------------------------------------------------
#define LN_ROWS 32

__global__ __launch_bounds__(128)
void ln_linear_kernel(const float* __restrict__ x,
                      const float* __restrict__ gamma,
                      const float* __restrict__ beta,
                      const float* __restrict__ W,    // [128 in][128 out]
                      const float* __restrict__ blin, // [128]
                      int dst_sel, int rowsPerL, int perN)
{
    __shared__ float xn_s[LN_ROWS][132];   // pad 132: rows hit distinct banks
    const int tid   = threadIdx.x;
    const int warp  = tid >> 5;
    const int lane  = tid & 31;
    const int rbase = blockIdx.x * LN_ROWS;

    float* __restrict__ out = (dst_sel == 0) ? g_qp : (dst_sel == 1) ? g_kp : g_vp;

    const float g0 = gamma[lane],      g1 = gamma[lane + 32],
                g2 = gamma[lane + 64], g3 = gamma[lane + 96];
    const float b0 = beta[lane],       b1 = beta[lane + 32],
                b2 = beta[lane + 64],  b3 = beta[lane + 96];

    // Phase 1: each warp normalizes 8 rows via shuffle reductions.
    #pragma unroll
    for (int rr = 0; rr < 8; rr++) {
        const int r   = warp * 8 + rr;
        const int row = rbase + r;
        const int L   = row / rowsPerL;
        const int N   = row - L * rowsPerL;
        const int nn  = N / perN;
        const int wi  = N - nn * perN;
        const float* xr = x + ((nn * 64 + L) * perN + wi) * D;

        const float v0 = xr[lane],      v1 = xr[lane + 32],
                    v2 = xr[lane + 64], v3 = xr[lane + 96];
        float s = v0 + v1 + v2 + v3;
        #pragma unroll
        for (int o = 16; o; o >>= 1) s += __shfl_xor_sync(0xffffffffu, s, o);
        const float mu = s * (1.0f / 128.0f);
        const float d0 = v0 - mu, d1 = v1 - mu, d2 = v2 - mu, d3 = v3 - mu;
        float sq = d0 * d0 + d1 * d1 + d2 * d2 + d3 * d3;
        #pragma unroll
        for (int o = 16; o; o >>= 1) sq += __shfl_xor_sync(0xffffffffu, sq, o);
        const float rstd = rsqrtf(sq * (1.0f / 128.0f) + 1e-5f);

        xn_s[r][lane]      = d0 * rstd * g0 + b0;
        xn_s[r][lane + 32] = d1 * rstd * g1 + b1;
        xn_s[r][lane + 64] = d2 * rstd * g2 + b2;
        xn_s[r][lane + 96] = d3 * rstd * g3 + b3;
    }
    __syncthreads();

    // Phase 2: thread (rt, ct) owns rows [rt*4, rt*4+4), cols [ct*8, ct*8+8).
    const int rt = tid >> 4;
    const int c8 = (tid & 15) * 8;

    u64 acc2[4][4];
    {
        const u64* bp2 = (const u64*)(blin + c8);
        u64 bb[4];
        #pragma unroll
        for (int p = 0; p < 4; p++) bb[p] = bp2[p];
        #pragma unroll
        for (int r = 0; r < 4; r++)
            #pragma unroll
            for (int p = 0; p < 4; p++) acc2[r][p] = bb[p];
    }

    #pragma unroll 4
    for (int j = 0; j < 128; j++) {
        const u64* wp = (const u64*)(W + j * 128 + c8);
        u64 w2[4];
        #pragma unroll
        for (int p = 0; p < 4; p++) w2[p] = wp[p];
        #pragma unroll
        for (int r = 0; r < 4; r++) {
            const float xv = xn_s[rt * 4 + r][j];
            const u64 x2 = pack2(xv, xv);
            #pragma unroll
            for (int p = 0; p < 4; p++) acc2[r][p] = fma2(x2, w2[p], acc2[r][p]);
        }
    }

    #pragma unroll
    for (int r = 0; r < 4; r++) {
        u64* op = (u64*)(out + (rbase + rt * 4 + r) * D + c8);
        #pragma unroll
        for (int p = 0; p < 4; p++) op[p] = acc2[r][p];
    }
}

// ---------------------------------------------------------------------------
// Kernel B: attention. Grid 512 = 4 heads * 64 L * 2 q-tiles, 128 thr/block.
// Thread pair (t, t^1) shares 3 q rows; even thread handles dh[0:16),
// odd dh[16:32). Dot halves combined with one shfl_xor per row per key.
// Each 8 LDS.128 per key now feeds 48 FFMA2 -> FMA-bound.
// Softmax without max-subtraction (|s| small, fp32 exp safe).
// ---------------------------------------------------------------------------
#define KCHUNK 96

__global__ __launch_bounds__(128, 3)
void attn_kernel(const float* __restrict__ scale_ptr)
{
    __shared__ float4 ks4[KCHUNK * 8];
    __shared__ float4 vs4[KCHUNK * 8];

    const int bx   = blockIdx.x;
    const int h    = bx & 3;
    const int l    = (bx >> 2) & 63;
    const int qt   = bx >> 8;          // 0..1
    const int tid  = threadIdx.x;
    const int pair = tid >> 1;         // 0..63
    const int half = tid & 1;

    const float coef = scale_ptr[0] * 0.17677669529663687f; // attn_scale * dh^-0.5

    // q fragments, pre-scaled by coef: rows qt*192 + pair + {0,64,128}
    u64 qr[3][8];
    #pragma unroll
    for (int r = 0; r < 3; r++) {
        const float4* qp = (const float4*)(g_qp +
            (l * 384 + qt * 192 + pair + r * 64) * D + h * 32 + half * 16);
        #pragma unroll
        for (int i = 0; i < 4; i++) {
            float4 t = qp[i];
            qr[r][2 * i]     = pack2(t.x * coef, t.y * coef);
            qr[r][2 * i + 1] = pack2(t.z * coef, t.w * coef);
        }
    }

    u64 acc[3][8];
    #pragma unroll
    for (int r = 0; r < 3; r++)
        #pragma unroll
        for (int i = 0; i < 8; i++) acc[r][i] = 0ULL;
    float lsum[3] = {0.0f, 0.0f, 0.0f};

    const float* kbase = g_kp + (l * 480) * D + h * 32;
    const float* vbase = g_vp + (l * 480) * D + h * 32;

    for (int c0 = 0; c0 < 480; c0 += KCHUNK) {
        __syncthreads();
        #pragma unroll
        for (int i = 0; i < (KCHUNK * 8) / 128; i++) {   // 6 iters
            const int idx = tid + i * 128;
            const int row = idx >> 3;
            const int c4  = idx & 7;
            ks4[idx] = *(const float4*)(kbase + (c0 + row) * D + c4 * 4);
            vs4[idx] = *(const float4*)(vbase + (c0 + row) * D + c4 * 4);
        }
        __syncthreads();

        #pragma unroll 4
        for (int kk = 0; kk < KCHUNK; kk++) {
            const u64* kr = (const u64*)(ks4 + kk * 8 + half * 4);
            u64 kf[8];
            #pragma unroll
            for (int i = 0; i < 8; i++) kf[i] = kr[i];

            float p[3];
            #pragma unroll
            for (int r = 0; r < 3; r++) {
                u64 s2 = 0ULL;
                #pragma unroll
                for (int i = 0; i < 8; i++) s2 = fma2(qr[r][i], kf[i], s2);
                const float2 sp = unpack2(s2);
                const float hsum = sp.x + sp.y;
                const float tot = hsum + __shfl_xor_sync(0xffffffffu, hsum, 1);
                p[r] = __expf(tot);
                lsum[r] += p[r];
            }

            const u64* vr = (const u64*)(vs4 + kk * 8 + half * 4);
            u64 vf[8];
            #pragma unroll
            for (int i = 0; i < 8; i++) vf[i] = vr[i];
            #pragma unroll
            for (int r = 0; r < 3; r++) {
                const u64 p2 = pack2(p[r], p[r]);
                #pragma unroll
                for (int i = 0; i < 8; i++) acc[r][i] = fma2(p2, vf[i], acc[r][i]);
            }
        }
    }

    #pragma unroll
    for (int r = 0; r < 3; r++) {
        const float inv = 1.0f / lsum[r];
        const u64 inv2 = pack2(inv, inv);
        u64* op = (u64*)(g_att +
            (l * 384 + qt * 192 + pair + r * 64) * D + h * 32 + half * 16);
        #pragma unroll
        for (int i = 0; i < 8; i++) op[i] = mul2(acc[r][i], inv2);
    }
}

// ---------------------------------------------------------------------------
// Kernel C: mean over n (commutes with affine proj) + Wp + bp + skip.
// ---------------------------------------------------------------------------
__global__ __launch_bounds__(128)
void proj_kernel(const float* __restrict__ Wp,
                 const float* __restrict__ bp,
                 const float* __restrict__ skip,
                 float* __restrict__ out)
{
    __shared__ float ab[16][128];
    const int tid   = threadIdx.x;
    const int obase = blockIdx.x * 16;

    #pragma unroll
    for (int r = 0; r < 16; r++) {
        const int o  = obase + r;
        const int L  = o >> 6;
        const int wi = o & 63;
        float s = 0.0f;
        #pragma unroll
        for (int n = 0; n < 6; n++)
            s += g_att[(L * 384 + n * 64 + wi) * D + tid];
        ab[r][tid] = s * (1.0f / 6.0f);
    }
    __syncthreads();

    const int c = tid;
    float acc[16];
    const float bb = bp[c];
    #pragma unroll
    for (int r = 0; r < 16; r++) acc[r] = bb;

    #pragma unroll 4
    for (int j = 0; j < 128; j++) {
        const float w = Wp[j * 128 + c];
        #pragma unroll
        for (int r = 0; r < 16; r++) acc[r] = fmaf(ab[r][j], w, acc[r]);
    }
    #pragma unroll
    for (int r = 0; r < 16; r++) {
        const int o = obase + r;
        out[o * D + c] = acc[r] + skip[o * D + c];
    }
}

// ---------------------------------------------------------------------------
extern "C" void kernel_launch(void* const* d_in, const int* in_sizes, int n_in,
                              void* d_out, int out_size)
{
    const float* q          = (const float*)d_in[0];
    const float* k          = (const float*)d_in[1];
    const float* v          = (const float*)d_in[2];
    const float* skip       = (const float*)d_in[3];
    const float* attn_scale = (const float*)d_in[4];
    const float* lnq_g = (const float*)d_in[5];
    const float* lnq_b = (const float*)d_in[6];
    const float* Wq    = (const float*)d_in[7];
    const float* bq    = (const float*)d_in[8];
    const float* lnk_g = (const float*)d_in[9];
    const float* lnk_b = (const float*)d_in[10];
    const float* Wk    = (const float*)d_in[11];
    const float* bk    = (const float*)d_in[12];
    const float* lnv_g = (const float*)d_in[13];
    const float* lnv_b = (const float*)d_in[14];
    const float* Wv    = (const float*)d_in[15];
    const float* bv    = (const float*)d_in[16];
    const float* Wp    = (const float*)d_in[17];
    const float* bp    = (const float*)d_in[18];
    float* out = (float*)d_out;

    ln_linear_kernel<<<NQ_ROWS / LN_ROWS, 128>>>(q, lnq_g, lnq_b, Wq, bq, 0, 384, 64);
    ln_linear_kernel<<<NK_ROWS / LN_ROWS, 128>>>(k, lnk_g, lnk_b, Wk, bk, 1, 480, 80);
    ln_linear_kernel<<<NK_ROWS / LN_ROWS, 128>>>(v, lnv_g, lnv_b, Wv, bv, 2, 480, 80);

    attn_kernel<<<512, 128>>>(attn_scale);

    proj_kernel<<<4096 / 16, 128>>>(Wp, bp, skip, out);
}

// round 4
// speedup vs baseline: 1.2657x; 1.2597x over previous
#include <cuda_runtime.h>

// ---------------------------------------------------------------------------
// CrossViewSwapAttention — fp32, f32x2 FMA-bound design.
//   q: (1,6,8,8,8,8,128)   -> qf  (L=64, Nq=384, d=128)
//   k,v: (1,6,8,8,8,10,128)-> kf  (L=64, Nk=480, d=128)
//   heads m=4, dh=32, inner=128; out: (1,8,8,8,8,128)
// ---------------------------------------------------------------------------

#define NQ_ROWS  24576   // 64*384
#define NK_ROWS  30720   // 64*480
#define D        128

__device__ float g_qp [NQ_ROWS * D];
__device__ float g_kp [NK_ROWS * D];
__device__ float g_vp [NK_ROWS * D];
__device__ float g_att[NQ_ROWS * D];

typedef unsigned long long u64;

__device__ __forceinline__ u64 fma2(u64 a, u64 b, u64 c) {
    u64 d;
    asm("fma.rn.f32x2 %0, %1, %2, %3;" : "=l"(d) : "l"(a), "l"(b), "l"(c));
    return d;
}
__device__ __forceinline__ u64 mul2(u64 a, u64 b) {
    u64 d;
    asm("mul.rn.f32x2 %0, %1, %2;" : "=l"(d) : "l"(a), "l"(b));
    return d;
}
__device__ __forceinline__ u64 pack2(float x, float y) {
    u64 d;
    asm("mov.b64 %0, {%1, %2};" : "=l"(d) : "f"(x), "f"(y));
    return d;
}
__device__ __forceinline__ float2 unpack2(u64 v) {
    float2 r;
    asm("mov.b64 {%0, %1}, %2;" : "=f"(r.x), "=f"(r.y) : "l"(v));
    return r;
}

// ---------------------------------------------------------------------------
// Kernel A: fused LayerNorm + Linear for q, k AND v in one launch.
// 64 rows per block; blockIdx selects the tensor segment.
//   blocks [0,384)    -> q  (rowsPerL=384, perN=64)
//   blocks [384,864)  -> k  (rowsPerL=480, perN=80)
//   blocks [864,1344) -> v
// Phase 2: 8 row-groups x 16 col-groups; thread tile 8 rows x 8 cols,
// j processed in pairs (one LDS.64 broadcast covers x[r][j], x[r][j+1]).
// W read straight from global (L1-resident after first pass on each SM).
// ---------------------------------------------------------------------------
#define LN_ROWS 64

__global__ __launch_bounds__(128)
void ln_all_kernel(const float* __restrict__ q,
                   const float* __restrict__ k,
                   const float* __restrict__ v,
                   const float* __restrict__ lnq_g, const float* __restrict__ lnq_b,
                   const float* __restrict__ Wq,    const float* __restrict__ bq,
                   const float* __restrict__ lnk_g, const float* __restrict__ lnk_b,
                   const float* __restrict__ Wk,    const float* __restrict__ bk,
                   const float* __restrict__ lnv_g, const float* __restrict__ lnv_b,
                   const float* __restrict__ Wv,    const float* __restrict__ bv)
{
    __shared__ float xn_s[LN_ROWS][132];   // row stride 132 floats (528B, 8B-aligned)
    const int bx   = blockIdx.x;
    const int tid  = threadIdx.x;
    const int warp = tid >> 5;
    const int lane = tid & 31;

    const float *x, *gamma, *beta, *W, *blin;
    float* out;
    int rowsPerL, perN, rbase;
    if (bx < 384) {
        x = q; gamma = lnq_g; beta = lnq_b; W = Wq; blin = bq;
        out = g_qp; rowsPerL = 384; perN = 64; rbase = bx * LN_ROWS;
    } else if (bx < 864) {
        x = k; gamma = lnk_g; beta = lnk_b; W = Wk; blin = bk;
        out = g_kp; rowsPerL = 480; perN = 80; rbase = (bx - 384) * LN_ROWS;
    } else {
        x = v; gamma = lnv_g; beta = lnv_b; W = Wv; blin = bv;
        out = g_vp; rowsPerL = 480; perN = 80; rbase = (bx - 864) * LN_ROWS;
    }

    const float g0 = gamma[lane],      g1 = gamma[lane + 32],
                g2 = gamma[lane + 64], g3 = gamma[lane + 96];
    const float b0 = beta[lane],       b1 = beta[lane + 32],
                b2 = beta[lane + 64],  b3 = beta[lane + 96];

    // Phase 1: each warp normalizes 16 rows via shuffle reductions.
    #pragma unroll 4
    for (int rr = 0; rr < 16; rr++) {
        const int r   = warp * 16 + rr;
        const int row = rbase + r;
        const int L   = row / rowsPerL;
        const int N   = row - L * rowsPerL;
        const int nn  = N / perN;
        const int wi  = N - nn * perN;
        const float* xr = x + ((nn * 64 + L) * perN + wi) * D;

        const float v0 = xr[lane],      v1 = xr[lane + 32],
                    v2 = xr[lane + 64], v3 = xr[lane + 96];
        float s = v0 + v1 + v2 + v3;
        #pragma unroll
        for (int o = 16; o; o >>= 1) s += __shfl_xor_sync(0xffffffffu, s, o);
        const float mu = s * (1.0f / 128.0f);
        const float d0 = v0 - mu, d1 = v1 - mu, d2 = v2 - mu, d3 = v3 - mu;
        float sq = d0 * d0 + d1 * d1 + d2 * d2 + d3 * d3;
        #pragma unroll
        for (int o = 16; o; o >>= 1) sq += __shfl_xor_sync(0xffffffffu, sq, o);
        const float rstd = rsqrtf(sq * (1.0f / 128.0f) + 1e-5f);

        xn_s[r][lane]      = d0 * rstd * g0 + b0;
        xn_s[r][lane + 32] = d1 * rstd * g1 + b1;
        xn_s[r][lane + 64] = d2 * rstd * g2 + b2;
        xn_s[r][lane + 96] = d3 * rstd * g3 + b3;
    }
    __syncthreads();

    // Phase 2: thread (rt, ct) owns rows [rt*8, rt*8+8), cols [ct*8, ct*8+8).
    const int rt = tid >> 4;         // 0..7
    const int c8 = (tid & 15) * 8;   // 0..120

    u64 acc2[8][4];
    {
        const u64* bp2 = (const u64*)(blin + c8);
        u64 bb[4];
        #pragma unroll
        for (int p = 0; p < 4; p++) bb[p] = bp2[p];
        #pragma unroll
        for (int r = 0; r < 8; r++)
            #pragma unroll
            for (int p = 0; p < 4; p++) acc2[r][p] = bb[p];
    }

    #pragma unroll 2
    for (int j = 0; j < 128; j += 2) {
        const u64* wp0 = (const u64*)(W + j * 128 + c8);
        const u64* wp1 = (const u64*)(W + (j + 1) * 128 + c8);
        u64 w0[4], w1[4];
        #pragma unroll
        for (int p = 0; p < 4; p++) { w0[p] = wp0[p]; w1[p] = wp1[p]; }

        #pragma unroll
        for (int r = 0; r < 8; r++) {
            const float2 xv = unpack2(*(const u64*)&xn_s[rt * 8 + r][j]);
            const u64 x0 = pack2(xv.x, xv.x);
            const u64 x1 = pack2(xv.y, xv.y);
            #pragma unroll
            for (int p = 0; p < 4; p++) {
                acc2[r][p] = fma2(x0, w0[p], acc2[r][p]);
                acc2[r][p] = fma2(x1, w1[p], acc2[r][p]);
            }
        }
    }

    #pragma unroll
    for (int r = 0; r < 8; r++) {
        u64* op = (u64*)(out + (rbase + rt * 8 + r) * D + c8);
        #pragma unroll
        for (int p = 0; p < 4; p++) op[p] = acc2[r][p];
    }
}

// ---------------------------------------------------------------------------
// Kernel B: attention. Grid 768 = 4 heads * 64 L * 3 q-tiles, 128 thr/block.
// Thread pair (t, t^1) shares 2 q rows; even thread handles dh[0:16),
// odd dh[16:32); dot halves combined with one shfl_xor per row per key.
// regs <= 128 -> 4 blocks/SM for latency hiding.
// ---------------------------------------------------------------------------
#define KCHUNK 96

__global__ __launch_bounds__(128, 4)
void attn_kernel(const float* __restrict__ scale_ptr)
{
    __shared__ float4 ks4[KCHUNK * 8];
    __shared__ float4 vs4[KCHUNK * 8];

    const int bx   = blockIdx.x;
    const int h    = bx & 3;
    const int l    = (bx >> 2) & 63;
    const int qt   = bx >> 8;          // 0..2
    const int tid  = threadIdx.x;
    const int pair = tid >> 1;         // 0..63
    const int half = tid & 1;

    const float coef = scale_ptr[0] * 0.17677669529663687f; // attn_scale * dh^-0.5

    // q fragments, pre-scaled: rows qt*128 + pair + {0,64}
    u64 qr[2][8];
    #pragma unroll
    for (int r = 0; r < 2; r++) {
        const float4* qp = (const float4*)(g_qp +
            (l * 384 + qt * 128 + pair + r * 64) * D + h * 32 + half * 16);
        #pragma unroll
        for (int i = 0; i < 4; i++) {
            float4 t = qp[i];
            qr[r][2 * i]     = pack2(t.x * coef, t.y * coef);
            qr[r][2 * i + 1] = pack2(t.z * coef, t.w * coef);
        }
    }

    u64 acc[2][8];
    #pragma unroll
    for (int r = 0; r < 2; r++)
        #pragma unroll
        for (int i = 0; i < 8; i++) acc[r][i] = 0ULL;
    float lsum[2] = {0.0f, 0.0f};

    const float* kbase = g_kp + (l * 480) * D + h * 32;
    const float* vbase = g_vp + (l * 480) * D + h * 32;

    for (int c0 = 0; c0 < 480; c0 += KCHUNK) {
        __syncthreads();
        #pragma unroll
        for (int i = 0; i < (KCHUNK * 8) / 128; i++) {   // 6 iters
            const int idx = tid + i * 128;
            const int row = idx >> 3;
            const int c4  = idx & 7;
            ks4[idx] = *(const float4*)(kbase + (c0 + row) * D + c4 * 4);
            vs4[idx] = *(const float4*)(vbase + (c0 + row) * D + c4 * 4);
        }
        __syncthreads();

        #pragma unroll 4
        for (int kk = 0; kk < KCHUNK; kk++) {
            const u64* kr = (const u64*)(ks4 + kk * 8 + half * 4);
            u64 kf[8];
            #pragma unroll
            for (int i = 0; i < 8; i++) kf[i] = kr[i];

            float p[2];
            #pragma unroll
            for (int r = 0; r < 2; r++) {
                u64 s2 = 0ULL;
                #pragma unroll
                for (int i = 0; i < 8; i++) s2 = fma2(qr[r][i], kf[i], s2);
                const float2 sp = unpack2(s2);
                const float hsum = sp.x + sp.y;
                const float tot = hsum + __shfl_xor_sync(0xffffffffu, hsum, 1);
                p[r] = __expf(tot);
                lsum[r] += p[r];
            }

            const u64* vr = (const u64*)(vs4 + kk * 8 + half * 4);
            u64 vf[8];
            #pragma unroll
            for (int i = 0; i < 8; i++) vf[i] = vr[i];
            #pragma unroll
            for (int r = 0; r < 2; r++) {
                const u64 p2 = pack2(p[r], p[r]);
                #pragma unroll
                for (int i = 0; i < 8; i++) acc[r][i] = fma2(p2, vf[i], acc[r][i]);
            }
        }
    }

    #pragma unroll
    for (int r = 0; r < 2; r++) {
        const float inv = 1.0f / lsum[r];
        const u64 inv2 = pack2(inv, inv);
        u64* op = (u64*)(g_att +
            (l * 384 + qt * 128 + pair + r * 64) * D + h * 32 + half * 16);
        #pragma unroll
        for (int i = 0; i < 8; i++) op[i] = mul2(acc[r][i], inv2);
    }
}

// ---------------------------------------------------------------------------
// Kernel C: mean over n (commutes with affine proj) + Wp + bp + skip.
// ---------------------------------------------------------------------------
__global__ __launch_bounds__(128)
void proj_kernel(const float* __restrict__ Wp,
                 const float* __restrict__ bp,
                 const float* __restrict__ skip,
                 float* __restrict__ out)
{
    __shared__ float ab[16][128];
    const int tid   = threadIdx.x;
    const int obase = blockIdx.x * 16;

    #pragma unroll
    for (int r = 0; r < 16; r++) {
        const int o  = obase + r;
        const int L  = o >> 6;
        const int wi = o & 63;
        float s = 0.0f;
        #pragma unroll
        for (int n = 0; n < 6; n++)
            s += g_att[(L * 384 + n * 64 + wi) * D + tid];
        ab[r][tid] = s * (1.0f / 6.0f);
    }
    __syncthreads();

    const int c = tid;
    float acc[16];
    const float bb = bp[c];
    #pragma unroll
    for (int r = 0; r < 16; r++) acc[r] = bb;

    #pragma unroll 4
    for (int j = 0; j < 128; j++) {
        const float w = Wp[j * 128 + c];
        #pragma unroll
        for (int r = 0; r < 16; r++) acc[r] = fmaf(ab[r][j], w, acc[r]);
    }
    #pragma unroll
    for (int r = 0; r < 16; r++) {
        const int o = obase + r;
        out[o * D + c] = acc[r] + skip[o * D + c];
    }
}

// ---------------------------------------------------------------------------
extern "C" void kernel_launch(void* const* d_in, const int* in_sizes, int n_in,
                              void* d_out, int out_size)
{
    const float* q          = (const float*)d_in[0];
    const float* k          = (const float*)d_in[1];
    const float* v          = (const float*)d_in[2];
    const float* skip       = (const float*)d_in[3];
    const float* attn_scale = (const float*)d_in[4];
    const float* lnq_g = (const float*)d_in[5];
    const float* lnq_b = (const float*)d_in[6];
    const float* Wq    = (const float*)d_in[7];
    const float* bq    = (const float*)d_in[8];
    const float* lnk_g = (const float*)d_in[9];
    const float* lnk_b = (const float*)d_in[10];
    const float* Wk    = (const float*)d_in[11];
    const float* bk    = (const float*)d_in[12];
    const float* lnv_g = (const float*)d_in[13];
    const float* lnv_b = (const float*)d_in[14];
    const float* Wv    = (const float*)d_in[15];
    const float* bv    = (const float*)d_in[16];
    const float* Wp    = (const float*)d_in[17];
    const float* bp    = (const float*)d_in[18];
    float* out = (float*)d_out;

    // One fused LN+Linear launch for q, k, v (384 + 480 + 480 blocks).
    ln_all_kernel<<<1344, 128>>>(q, k, v,
                                 lnq_g, lnq_b, Wq, bq,
                                 lnk_g, lnk_b, Wk, bk,
                                 lnv_g, lnv_b, Wv, bv);

    // Attention: 4 heads * 64 L * 3 q-tiles
    attn_kernel<<<768, 128>>>(attn_scale);

    // Mean over views + output projection + skip
    proj_kernel<<<4096 / 16, 128>>>(Wp, bp, skip, out);
}

// round 5
// speedup vs baseline: 1.4100x; 1.1140x over previous
#include <cuda_runtime.h>

// ---------------------------------------------------------------------------
// CrossViewSwapAttention — fp32, f32x2 FMA-bound design.
//   q: (1,6,8,8,8,8,128)   -> qf  (L=64, Nq=384, d=128)
//   k,v: (1,6,8,8,8,10,128)-> kf  (L=64, Nk=480, d=128)
//   heads m=4, dh=32, inner=128; out: (1,8,8,8,8,128)
// ---------------------------------------------------------------------------

#define NQ_ROWS  24576   // 64*384
#define NK_ROWS  30720   // 64*480
#define D        128

__device__ float g_qp [NQ_ROWS * D];
__device__ float g_kp [NK_ROWS * D];
__device__ float g_vp [NK_ROWS * D];
__device__ float g_att[NQ_ROWS * D];

typedef unsigned long long u64;

__device__ __forceinline__ u64 fma2(u64 a, u64 b, u64 c) {
    u64 d;
    asm("fma.rn.f32x2 %0, %1, %2, %3;" : "=l"(d) : "l"(a), "l"(b), "l"(c));
    return d;
}
__device__ __forceinline__ u64 mul2(u64 a, u64 b) {
    u64 d;
    asm("mul.rn.f32x2 %0, %1, %2;" : "=l"(d) : "l"(a), "l"(b));
    return d;
}
__device__ __forceinline__ u64 pack2(float x, float y) {
    u64 d;
    asm("mov.b64 %0, {%1, %2};" : "=l"(d) : "f"(x), "f"(y));
    return d;
}
__device__ __forceinline__ float2 unpack2(u64 v) {
    float2 r;
    asm("mov.b64 {%0, %1}, %2;" : "=f"(r.x), "=f"(r.y) : "l"(v));
    return r;
}
__device__ __forceinline__ float ex2(float x) {
    float r;
    asm("ex2.approx.f32 %0, %1;" : "=f"(r) : "f"(x));
    return r;
}

// ---------------------------------------------------------------------------
// Kernel A: fused LayerNorm + Linear for q, k AND v in one launch.
// 64 rows per block; blockIdx selects the tensor segment.
//   blocks [0,384)    -> q  (rowsPerL=384, perN=64)
//   blocks [384,864)  -> k  (rowsPerL=480, perN=80)
//   blocks [864,1344) -> v
// Normalized x is stored TRANSPOSED (xT[j][row]) so phase-2 LDS.128 reads
// give {x[r],x[r+1]} u64s directly usable as the f32x2 accumulator operand
// (acc vector spans a row pair; only W needs splatting).
// Per j per thread: 2 LDS.128 + 2 LDG.128 + 8 packs + 32 fma2 (73% fma2).
// ---------------------------------------------------------------------------
#define LN_ROWS 64
#define XT_STRIDE 68   // floats; 272B row: 16B-aligned, 4-way STS conflict only

__global__ __launch_bounds__(128)
void ln_all_kernel(const float* __restrict__ q,
                   const float* __restrict__ k,
                   const float* __restrict__ v,
                   const float* __restrict__ lnq_g, const float* __restrict__ lnq_b,
                   const float* __restrict__ Wq,    const float* __restrict__ bq,
                   const float* __restrict__ lnk_g, const float* __restrict__ lnk_b,
                   const float* __restrict__ Wk,    const float* __restrict__ bk,
                   const float* __restrict__ lnv_g, const float* __restrict__ lnv_b,
                   const float* __restrict__ Wv,    const float* __restrict__ bv)
{
    __shared__ float xT[128 * XT_STRIDE];   // xT[j][row], 34.8 KB
    const int bx   = blockIdx.x;
    const int tid  = threadIdx.x;
    const int warp = tid >> 5;
    const int lane = tid & 31;

    const float *x, *gamma, *beta, *W, *blin;
    float* out;
    int rowsPerL, perN, rbase;
    if (bx < 384) {
        x = q; gamma = lnq_g; beta = lnq_b; W = Wq; blin = bq;
        out = g_qp; rowsPerL = 384; perN = 64; rbase = bx * LN_ROWS;
    } else if (bx < 864) {
        x = k; gamma = lnk_g; beta = lnk_b; W = Wk; blin = bk;
        out = g_kp; rowsPerL = 480; perN = 80; rbase = (bx - 384) * LN_ROWS;
    } else {
        x = v; gamma = lnv_g; beta = lnv_b; W = Wv; blin = bv;
        out = g_vp; rowsPerL = 480; perN = 80; rbase = (bx - 864) * LN_ROWS;
    }

    const float g0 = gamma[lane],      g1 = gamma[lane + 32],
                g2 = gamma[lane + 64], g3 = gamma[lane + 96];
    const float b0 = beta[lane],       b1 = beta[lane + 32],
                b2 = beta[lane + 64],  b3 = beta[lane + 96];

    // Phase 1: each warp normalizes 16 rows, writes TRANSPOSED into xT.
    #pragma unroll 4
    for (int rr = 0; rr < 16; rr++) {
        const int r   = warp * 16 + rr;
        const int row = rbase + r;
        const int L   = row / rowsPerL;
        const int N   = row - L * rowsPerL;
        const int nn  = N / perN;
        const int wi  = N - nn * perN;
        const float* xr = x + ((nn * 64 + L) * perN + wi) * D;

        const float v0 = xr[lane],      v1 = xr[lane + 32],
                    v2 = xr[lane + 64], v3 = xr[lane + 96];
        float s = v0 + v1 + v2 + v3;
        #pragma unroll
        for (int o = 16; o; o >>= 1) s += __shfl_xor_sync(0xffffffffu, s, o);
        const float mu = s * (1.0f / 128.0f);
        const float d0 = v0 - mu, d1 = v1 - mu, d2 = v2 - mu, d3 = v3 - mu;
        float sq = d0 * d0 + d1 * d1 + d2 * d2 + d3 * d3;
        #pragma unroll
        for (int o = 16; o; o >>= 1) sq += __shfl_xor_sync(0xffffffffu, sq, o);
        const float rstd = rsqrtf(sq * (1.0f / 128.0f) + 1e-5f);

        xT[(lane)      * XT_STRIDE + r] = d0 * rstd * g0 + b0;
        xT[(lane + 32) * XT_STRIDE + r] = d1 * rstd * g1 + b1;
        xT[(lane + 64) * XT_STRIDE + r] = d2 * rstd * g2 + b2;
        xT[(lane + 96) * XT_STRIDE + r] = d3 * rstd * g3 + b3;
    }
    __syncthreads();

    // Phase 2: thread (rt, ct) owns row-pairs [rt*8 .. rt*8+8), cols [ct*8..+8).
    const int rt = tid >> 4;         // 0..7
    const int c8 = (tid & 15) * 8;   // 0..120

    u64 acc2[4][8];   // [row-pair][col] ; vector = {row 2rp, row 2rp+1}
    #pragma unroll
    for (int c = 0; c < 8; c++) {
        const float bb = blin[c8 + c];
        const u64 bb2 = pack2(bb, bb);
        #pragma unroll
        for (int rp = 0; rp < 4; rp++) acc2[rp][c] = bb2;
    }

    const float* xrow = xT + rt * 8;
    #pragma unroll 4
    for (int j = 0; j < 128; j++) {
        // x row-pairs: 8 consecutive floats -> 4 u64 {x[2rp], x[2rp+1]}
        const u64* xp = (const u64*)(xrow + j * XT_STRIDE);
        u64 xv[4];
        #pragma unroll
        for (int rp = 0; rp < 4; rp++) xv[rp] = xp[rp];

        const float4* wp = (const float4*)(W + j * 128 + c8);
        const float4 wa = wp[0], wb = wp[1];
        u64 ws[8];
        ws[0] = pack2(wa.x, wa.x); ws[1] = pack2(wa.y, wa.y);
        ws[2] = pack2(wa.z, wa.z); ws[3] = pack2(wa.w, wa.w);
        ws[4] = pack2(wb.x, wb.x); ws[5] = pack2(wb.y, wb.y);
        ws[6] = pack2(wb.z, wb.z); ws[7] = pack2(wb.w, wb.w);

        #pragma unroll
        for (int rp = 0; rp < 4; rp++)
            #pragma unroll
            for (int c = 0; c < 8; c++)
                acc2[rp][c] = fma2(xv[rp], ws[c], acc2[rp][c]);
    }

    // Epilogue: acc2[rp][c] = {C[2rp][c], C[2rp+1][c]} -> two rows per rp.
    #pragma unroll
    for (int rp = 0; rp < 4; rp++) {
        float r0[8], r1[8];
        #pragma unroll
        for (int c = 0; c < 8; c++) {
            const float2 t = unpack2(acc2[rp][c]);
            r0[c] = t.x; r1[c] = t.y;
        }
        float* o0 = out + (rbase + rt * 8 + 2 * rp)     * D + c8;
        float* o1 = out + (rbase + rt * 8 + 2 * rp + 1) * D + c8;
        ((float4*)o0)[0] = make_float4(r0[0], r0[1], r0[2], r0[3]);
        ((float4*)o0)[1] = make_float4(r0[4], r0[5], r0[6], r0[7]);
        ((float4*)o1)[0] = make_float4(r1[0], r1[1], r1[2], r1[3]);
        ((float4*)o1)[1] = make_float4(r1[4], r1[5], r1[6], r1[7]);
    }
}

// ---------------------------------------------------------------------------
// Kernel B: attention (measured-best 3-row config). Grid 512 = 4h*64L*2qt.
// Thread pair (t, t^1) shares 3 q rows; even thread dh[0:16), odd dh[16:32);
// dot halves combined via shfl_xor. q pre-scaled by attn_scale*dh^-0.5*log2e
// so softmax is a bare ex2.approx.
// ---------------------------------------------------------------------------
#define KCHUNK 96

__global__ __launch_bounds__(128, 3)
void attn_kernel(const float* __restrict__ scale_ptr)
{
    __shared__ float4 ks4[KCHUNK * 8];
    __shared__ float4 vs4[KCHUNK * 8];

    const int bx   = blockIdx.x;
    const int h    = bx & 3;
    const int l    = (bx >> 2) & 63;
    const int qt   = bx >> 8;          // 0..1
    const int tid  = threadIdx.x;
    const int pair = tid >> 1;         // 0..63
    const int half = tid & 1;

    // attn_scale * dh^-0.5 * log2(e)
    const float coef = scale_ptr[0] * 0.17677669529663687f * 1.4426950408889634f;

    u64 qr[3][8];
    #pragma unroll
    for (int r = 0; r < 3; r++) {
        const float4* qp = (const float4*)(g_qp +
            (l * 384 + qt * 192 + pair + r * 64) * D + h * 32 + half * 16);
        #pragma unroll
        for (int i = 0; i < 4; i++) {
            float4 t = qp[i];
            qr[r][2 * i]     = pack2(t.x * coef, t.y * coef);
            qr[r][2 * i + 1] = pack2(t.z * coef, t.w * coef);
        }
    }

    u64 acc[3][8];
    #pragma unroll
    for (int r = 0; r < 3; r++)
        #pragma unroll
        for (int i = 0; i < 8; i++) acc[r][i] = 0ULL;
    float lsum[3] = {0.0f, 0.0f, 0.0f};

    const float* kbase = g_kp + (l * 480) * D + h * 32;
    const float* vbase = g_vp + (l * 480) * D + h * 32;

    for (int c0 = 0; c0 < 480; c0 += KCHUNK) {
        __syncthreads();
        #pragma unroll
        for (int i = 0; i < (KCHUNK * 8) / 128; i++) {   // 6 iters
            const int idx = tid + i * 128;
            const int row = idx >> 3;
            const int c4  = idx & 7;
            ks4[idx] = *(const float4*)(kbase + (c0 + row) * D + c4 * 4);
            vs4[idx] = *(const float4*)(vbase + (c0 + row) * D + c4 * 4);
        }
        __syncthreads();

        #pragma unroll 4
        for (int kk = 0; kk < KCHUNK; kk++) {
            const u64* kr = (const u64*)(ks4 + kk * 8 + half * 4);
            u64 kf[8];
            #pragma unroll
            for (int i = 0; i < 8; i++) kf[i] = kr[i];

            float p[3];
            #pragma unroll
            for (int r = 0; r < 3; r++) {
                u64 sa = 0ULL, sb = 0ULL;
                #pragma unroll
                for (int i = 0; i < 4; i++) {
                    sa = fma2(qr[r][2 * i],     kf[2 * i],     sa);
                    sb = fma2(qr[r][2 * i + 1], kf[2 * i + 1], sb);
                }
                const float2 sx = unpack2(sa);
                const float2 sy = unpack2(sb);
                const float hsum = (sx.x + sx.y) + (sy.x + sy.y);
                const float tot = hsum + __shfl_xor_sync(0xffffffffu, hsum, 1);
                p[r] = ex2(tot);
                lsum[r] += p[r];
            }

            const u64* vr = (const u64*)(vs4 + kk * 8 + half * 4);
            u64 vf[8];
            #pragma unroll
            for (int i = 0; i < 8; i++) vf[i] = vr[i];
            #pragma unroll
            for (int r = 0; r < 3; r++) {
                const u64 p2 = pack2(p[r], p[r]);
                #pragma unroll
                for (int i = 0; i < 8; i++) acc[r][i] = fma2(p2, vf[i], acc[r][i]);
            }
        }
    }

    #pragma unroll
    for (int r = 0; r < 3; r++) {
        const float inv = 1.0f / lsum[r];
        const u64 inv2 = pack2(inv, inv);
        u64* op = (u64*)(g_att +
            (l * 384 + qt * 192 + pair + r * 64) * D + h * 32 + half * 16);
        #pragma unroll
        for (int i = 0; i < 8; i++) op[i] = mul2(acc[r][i], inv2);
    }
}

// ---------------------------------------------------------------------------
// Kernel C: mean over n (commutes with affine proj) + Wp + bp + skip.
// ---------------------------------------------------------------------------
__global__ __launch_bounds__(128)
void proj_kernel(const float* __restrict__ Wp,
                 const float* __restrict__ bp,
                 const float* __restrict__ skip,
                 float* __restrict__ out)
{
    __shared__ float ab[16][128];
    const int tid   = threadIdx.x;
    const int obase = blockIdx.x * 16;

    #pragma unroll
    for (int r = 0; r < 16; r++) {
        const int o  = obase + r;
        const int L  = o >> 6;
        const int wi = o & 63;
        float s = 0.0f;
        #pragma unroll
        for (int n = 0; n < 6; n++)
            s += g_att[(L * 384 + n * 64 + wi) * D + tid];
        ab[r][tid] = s * (1.0f / 6.0f);
    }
    __syncthreads();

    const int c = tid;
    float acc[16];
    const float bb = bp[c];
    #pragma unroll
    for (int r = 0; r < 16; r++) acc[r] = bb;

    #pragma unroll 4
    for (int j = 0; j < 128; j++) {
        const float w = Wp[j * 128 + c];
        #pragma unroll
        for (int r = 0; r < 16; r++) acc[r] = fmaf(ab[r][j], w, acc[r]);
    }
    #pragma unroll
    for (int r = 0; r < 16; r++) {
        const int o = obase + r;
        out[o * D + c] = acc[r] + skip[o * D + c];
    }
}

// ---------------------------------------------------------------------------
extern "C" void kernel_launch(void* const* d_in, const int* in_sizes, int n_in,
                              void* d_out, int out_size)
{
    const float* q          = (const float*)d_in[0];
    const float* k          = (const float*)d_in[1];
    const float* v          = (const float*)d_in[2];
    const float* skip       = (const float*)d_in[3];
    const float* attn_scale = (const float*)d_in[4];
    const float* lnq_g = (const float*)d_in[5];
    const float* lnq_b = (const float*)d_in[6];
    const float* Wq    = (const float*)d_in[7];
    const float* bq    = (const float*)d_in[8];
    const float* lnk_g = (const float*)d_in[9];
    const float* lnk_b = (const float*)d_in[10];
    const float* Wk    = (const float*)d_in[11];
    const float* bk    = (const float*)d_in[12];
    const float* lnv_g = (const float*)d_in[13];
    const float* lnv_b = (const float*)d_in[14];
    const float* Wv    = (const float*)d_in[15];
    const float* bv    = (const float*)d_in[16];
    const float* Wp    = (const float*)d_in[17];
    const float* bp    = (const float*)d_in[18];
    float* out = (float*)d_out;

    ln_all_kernel<<<1344, 128>>>(q, k, v,
                                 lnq_g, lnq_b, Wq, bq,
                                 lnk_g, lnk_b, Wk, bk,
                                 lnv_g, lnv_b, Wv, bv);

    attn_kernel<<<512, 128>>>(attn_scale);

    proj_kernel<<<4096 / 16, 128>>>(Wp, bp, skip, out);
}